// round 3
// baseline (speedup 1.0000x reference)
#include <cuda_runtime.h>
#include <math.h>

// Problem constants (fixed by the reference)
#define Nn   100000
#define Ee   1600000
#define INF  128
#define HIDF 64
#define NH   8
#define F1   512      // NH*HIDF
#define OUTF 64
#define ALPHA 0.2f
#define NB_SCAN ((Nn + 1023) / 1024)   // 98

// ---------------- device scratch (no allocations allowed) ----------------
__device__ float g_xp[Nn * INF];                 // 51.2 MB
__device__ float g_h1[(size_t)Nn * F1];          // 204.8 MB
__device__ float g_out1[(size_t)Nn * F1];        // 204.8 MB
__device__ float g_h2[Nn * OUTF];                // 25.6 MB
__device__ float g_Wcat[INF * F1];               // repacked head weights
__device__ float g_ssrc1[Nn * NH];
__device__ float g_sdst1[Nn * NH];
__device__ float g_ssrc2[Nn];
__device__ float g_sdst2[Nn];
__device__ int   g_counts[Nn];
__device__ int   g_fill[Nn];
__device__ int   g_rowptr[Nn + 1];
__device__ int   g_dst[Ee];
__device__ int   g_blksums[128];

// ---------------- CSR construction ----------------
__global__ void zero_kernel() {
    int i = blockIdx.x * blockDim.x + threadIdx.x;
    if (i < Nn) { g_counts[i] = 0; g_fill[i] = 0; }
}

__global__ void count_kernel(const int* __restrict__ src) {
    int e = blockIdx.x * blockDim.x + threadIdx.x;
    if (e < Ee) atomicAdd(&g_counts[src[e]], 1);
}

__global__ void scan_block_kernel() {
    __shared__ int sh[1024];
    int i = blockIdx.x * 1024 + threadIdx.x;
    int v = (i < Nn) ? g_counts[i] : 0;
    sh[threadIdx.x] = v;
    __syncthreads();
    #pragma unroll
    for (int off = 1; off < 1024; off <<= 1) {
        int t = (threadIdx.x >= off) ? sh[threadIdx.x - off] : 0;
        __syncthreads();
        sh[threadIdx.x] += t;
        __syncthreads();
    }
    if (i < Nn) g_rowptr[i] = sh[threadIdx.x] - v;   // exclusive within block
    if (threadIdx.x == 1023) g_blksums[blockIdx.x] = sh[1023];
}

__global__ void scan_top_kernel() {
    if (threadIdx.x == 0 && blockIdx.x == 0) {
        int s = 0;
        for (int i = 0; i < NB_SCAN; i++) { int v = g_blksums[i]; g_blksums[i] = s; s += v; }
    }
}

__global__ void scan_add_kernel() {
    int i = blockIdx.x * blockDim.x + threadIdx.x;
    if (i < Nn) g_rowptr[i] += g_blksums[i >> 10];
    if (i == 0) g_rowptr[Nn] = Ee;
}

__global__ void scatter_kernel(const int* __restrict__ src, const int* __restrict__ dst) {
    int e = blockIdx.x * blockDim.x + threadIdx.x;
    if (e < Ee) {
        int s = src[e];
        int pos = g_rowptr[s] + atomicAdd(&g_fill[s], 1);
        g_dst[pos] = dst[e];
    }
}

// ---------------- weight repack: Wcat[i][h*64+j] = W_heads[h][i][j] ----------------
__global__ void repack_kernel(const float* __restrict__ W_heads) {
    int t = blockIdx.x * blockDim.x + threadIdx.x;
    if (t >= INF * F1) return;
    int i = t / F1;
    int c = t - i * F1;
    int h = c >> 6;
    int j = c & 63;
    g_Wcat[t] = W_heads[(h * INF + i) * HIDF + j];
}

// ---------------- generic tiled fp32 GEMM: C[n,M] = A[n,K] @ B[K,M] (+bias) ----------------
// BM=BN=64, BK=16, 256 threads, 4x4 microtile
__global__ void gemm_kernel(const float* __restrict__ A, const float* __restrict__ B,
                            const float* __restrict__ bias, float* __restrict__ C,
                            int n, int K, int M) {
    __shared__ float As[16][68];   // [k][m], padded, float4-aligned (68 % 4 == 0)
    __shared__ float Bs[16][64];   // [k][n]
    int t  = threadIdx.x;
    int tx = t & 15, ty = t >> 4;
    int bm = blockIdx.y * 64;
    int bn = blockIdx.x * 64;

    int ar = t >> 2;            // 0..63  (A tile row)
    int ac = (t & 3) * 4;       // 0..12  (A tile col, float4)
    int br = t >> 4;            // 0..15  (B tile row)
    int bc = (t & 15) * 4;      // 0..60  (B tile col, float4)

    float acc[4][4] = {};
    int arow = bm + ar;
    bool arow_ok = arow < n;
    const float* Ap = A + (size_t)arow * K + ac;

    for (int k0 = 0; k0 < K; k0 += 16) {
        float4 av = arow_ok ? *(const float4*)(Ap + k0) : make_float4(0.f, 0.f, 0.f, 0.f);
        float4 bv = *(const float4*)(B + (size_t)(k0 + br) * M + bn + bc);
        __syncthreads();
        As[ac + 0][ar] = av.x; As[ac + 1][ar] = av.y;
        As[ac + 2][ar] = av.z; As[ac + 3][ar] = av.w;
        *(float4*)&Bs[br][bc] = bv;
        __syncthreads();
        #pragma unroll
        for (int kk = 0; kk < 16; kk++) {
            float a4[4], b4[4];
            *(float4*)a4 = *(const float4*)&As[kk][ty * 4];
            *(float4*)b4 = *(const float4*)&Bs[kk][tx * 4];
            #pragma unroll
            for (int i = 0; i < 4; i++)
                #pragma unroll
                for (int j = 0; j < 4; j++)
                    acc[i][j] += a4[i] * b4[j];
        }
    }

    int col = bn + tx * 4;
    float bsv[4] = {0.f, 0.f, 0.f, 0.f};
    if (bias) { *(float4*)bsv = *(const float4*)(bias + col); }
    #pragma unroll
    for (int i = 0; i < 4; i++) {
        int row = bm + ty * 4 + i;
        if (row < n) {
            float4 o;
            o.x = acc[i][0] + bsv[0];
            o.y = acc[i][1] + bsv[1];
            o.z = acc[i][2] + bsv[2];
            o.w = acc[i][3] + bsv[3];
            *(float4*)(C + (size_t)row * M + col) = o;
        }
    }
}

// ---------------- per-node scores layer 1: block per node, warp per head ----------------
__global__ void s1_kernel(const float* __restrict__ a_heads) {
    int node = blockIdx.x;
    int h    = threadIdx.x >> 5;
    int lane = threadIdx.x & 31;
    const float* base = g_h1 + (size_t)node * F1 + h * 64;
    const float* ah   = a_heads + h * 128;
    float v0 = base[lane], v1 = base[lane + 32];
    float ssrc = v0 * ah[lane]      + v1 * ah[lane + 32];
    float sdst = v0 * ah[64 + lane] + v1 * ah[96 + lane];
    #pragma unroll
    for (int off = 16; off; off >>= 1) {
        ssrc += __shfl_xor_sync(0xffffffffu, ssrc, off);
        sdst += __shfl_xor_sync(0xffffffffu, sdst, off);
    }
    if (lane == 0) {
        g_ssrc1[node * NH + h] = ssrc;
        g_sdst1[node * NH + h] = sdst;
    }
}

// ---------------- layer-1 aggregation: warp per node ----------------
__global__ void agg1_kernel() {
    int node = (blockIdx.x * blockDim.x + threadIdx.x) >> 5;
    if (node >= Nn) return;
    int lane = threadIdx.x & 31;
    int hl   = lane & 7;        // head whose weight this lane computes
    int hsel = lane >> 4;       // 0/1: which head within each 128-col chunk

    float ssrc = g_ssrc1[node * NH + hl];
    int beg = g_rowptr[node], end = g_rowptr[node + 1];

    float4 acc[4];
    float  rs[4];
    #pragma unroll
    for (int k = 0; k < 4; k++) { acc[k] = make_float4(0.f,0.f,0.f,0.f); rs[k] = 0.f; }

    for (int j = beg; j < end; j++) {
        int d = g_dst[j];
        float sc = ssrc + g_sdst1[d * NH + hl];
        float lr = sc > 0.f ? sc : ALPHA * sc;
        float w8 = __expf(-lr);
        const float4* hp = (const float4*)(g_h1 + (size_t)d * F1);
        #pragma unroll
        for (int k = 0; k < 4; k++) {
            float w = __shfl_sync(0xffffffffu, w8, 2 * k + hsel);
            float4 v = hp[k * 32 + lane];
            acc[k].x += w * v.x; acc[k].y += w * v.y;
            acc[k].z += w * v.z; acc[k].w += w * v.w;
            rs[k] += w;
        }
    }

    float* outp = g_out1 + (size_t)node * F1;
    #pragma unroll
    for (int k = 0; k < 4; k++) {
        float inv = 1.f / (rs[k] + 1e-16f);
        float4 o;
        o.x = acc[k].x * inv; o.y = acc[k].y * inv;
        o.z = acc[k].z * inv; o.w = acc[k].w * inv;
        // ELU
        o.x = o.x > 0.f ? o.x : expm1f(o.x);
        o.y = o.y > 0.f ? o.y : expm1f(o.y);
        o.z = o.z > 0.f ? o.z : expm1f(o.z);
        o.w = o.w > 0.f ? o.w : expm1f(o.w);
        *(float4*)(outp + k * 128 + lane * 4) = o;
    }
}

// ---------------- per-node scores layer 2: warp per node ----------------
__global__ void s2_kernel(const float* __restrict__ a_end) {
    int node = (blockIdx.x * blockDim.x + threadIdx.x) >> 5;
    if (node >= Nn) return;
    int lane = threadIdx.x & 31;
    const float* base = g_h2 + (size_t)node * OUTF;
    float v0 = base[lane], v1 = base[lane + 32];
    float ssrc = v0 * a_end[lane]      + v1 * a_end[lane + 32];
    float sdst = v0 * a_end[64 + lane] + v1 * a_end[96 + lane];
    #pragma unroll
    for (int off = 16; off; off >>= 1) {
        ssrc += __shfl_xor_sync(0xffffffffu, ssrc, off);
        sdst += __shfl_xor_sync(0xffffffffu, sdst, off);
    }
    if (lane == 0) { g_ssrc2[node] = ssrc; g_sdst2[node] = sdst; }
}

// ---------------- layer-2 aggregation + softmax: warp per node ----------------
__global__ void agg2_kernel(float* __restrict__ out) {
    int node = (blockIdx.x * blockDim.x + threadIdx.x) >> 5;
    if (node >= Nn) return;
    int lane = threadIdx.x & 31;

    float ss = g_ssrc2[node];
    int beg = g_rowptr[node], end = g_rowptr[node + 1];
    float a0 = 0.f, a1 = 0.f, rs = 0.f;
    for (int j = beg; j < end; j++) {
        int d = g_dst[j];
        float sc = ss + g_sdst2[d];
        float lr = sc > 0.f ? sc : ALPHA * sc;
        float w = __expf(-lr);
        const float* hp = g_h2 + (size_t)d * OUTF;
        a0 += w * hp[lane];
        a1 += w * hp[lane + 32];
        rs += w;
    }
    float inv = 1.f / (rs + 1e-16f);
    float v0 = a0 * inv, v1 = a1 * inv;

    // softmax over the 64 outputs (2 per lane)
    float m = fmaxf(v0, v1);
    #pragma unroll
    for (int off = 16; off; off >>= 1) m = fmaxf(m, __shfl_xor_sync(0xffffffffu, m, off));
    float e0 = __expf(v0 - m), e1 = __expf(v1 - m);
    float s = e0 + e1;
    #pragma unroll
    for (int off = 16; off; off >>= 1) s += __shfl_xor_sync(0xffffffffu, s, off);
    float invs = 1.f / s;
    out[(size_t)node * OUTF + lane]      = e0 * invs;
    out[(size_t)node * OUTF + lane + 32] = e1 * invs;
}

// ---------------- launch ----------------
extern "C" void kernel_launch(void* const* d_in, const int* in_sizes, int n_in,
                              void* d_out, int out_size) {
    const float* x       = (const float*)d_in[0];
    const int*   edges   = (const int*)  d_in[1];
    const float* W0      = (const float*)d_in[2];
    const float* b0      = (const float*)d_in[3];
    const float* W_heads = (const float*)d_in[4];
    const float* a_heads = (const float*)d_in[5];
    const float* W_end   = (const float*)d_in[6];
    const float* a_end   = (const float*)d_in[7];
    float* out = (float*)d_out;
    const int* src = edges;
    const int* dst = edges + Ee;

    float *p_xp, *p_h1, *p_out1, *p_h2, *p_Wcat;
    cudaGetSymbolAddress((void**)&p_xp,   g_xp);
    cudaGetSymbolAddress((void**)&p_h1,   g_h1);
    cudaGetSymbolAddress((void**)&p_out1, g_out1);
    cudaGetSymbolAddress((void**)&p_h2,   g_h2);
    cudaGetSymbolAddress((void**)&p_Wcat, g_Wcat);

    // CSR build
    zero_kernel<<<(Nn + 255) / 256, 256>>>();
    count_kernel<<<(Ee + 255) / 256, 256>>>(src);
    scan_block_kernel<<<NB_SCAN, 1024>>>();
    scan_top_kernel<<<1, 32>>>();
    scan_add_kernel<<<(Nn + 255) / 256, 256>>>();
    scatter_kernel<<<(Ee + 255) / 256, 256>>>(src, dst);

    // weight repack (independent of CSR, cheap)
    repack_kernel<<<(INF * F1 + 255) / 256, 256>>>(W_heads);

    // xp = x @ W0 + b0
    {
        dim3 grid(INF / 64, (Nn + 63) / 64);
        gemm_kernel<<<grid, 256>>>(x, W0, b0, p_xp, Nn, INF, INF);
    }
    // h1 = xp @ Wcat   (all 8 heads fused, [N,512])
    {
        dim3 grid(F1 / 64, (Nn + 63) / 64);
        gemm_kernel<<<grid, 256>>>(p_xp, p_Wcat, nullptr, p_h1, Nn, INF, F1);
    }
    // per-node scores, layer 1
    s1_kernel<<<Nn, 256>>>(a_heads);
    // layer-1 aggregation + ELU -> out1 [N,512]
    agg1_kernel<<<(Nn + 7) / 8, 256>>>();

    // h2 = out1 @ W_end  [N,64]
    {
        dim3 grid(OUTF / 64, (Nn + 63) / 64);
        gemm_kernel<<<grid, 256>>>(p_out1, W_end, nullptr, p_h2, Nn, F1, OUTF);
    }
    // per-node scores, layer 2
    s2_kernel<<<(Nn + 7) / 8, 256>>>(a_end);
    // layer-2 aggregation + softmax -> output
    agg2_kernel<<<(Nn + 7) / 8, 256>>>(out);
}

// round 4
// speedup vs baseline: 1.0046x; 1.0046x over previous
#include <cuda_runtime.h>
#include <math.h>

// Problem constants (fixed by the reference)
#define Nn   100000
#define Ee   1600000
#define INF  128
#define HIDF 64
#define NH   8
#define F1   512      // NH*HIDF
#define OUTF 64
#define ALPHA 0.2f
#define NB_SCAN ((Nn + 1023) / 1024)   // 98

// ---------------- device scratch (no allocations allowed) ----------------
__device__ float g_xp[Nn * INF];                 // 51.2 MB
__device__ float g_h1[(size_t)Nn * F1];          // 204.8 MB
__device__ float g_out1[(size_t)Nn * F1];        // 204.8 MB
__device__ float g_h2[Nn * OUTF];                // 25.6 MB
__device__ float g_Wcat[INF * F1];               // repacked head weights
__device__ float g_ssrc1[Nn * NH];
__device__ float g_sdst1[Nn * NH];
__device__ float g_ssrc2[Nn];
__device__ float g_sdst2[Nn];
__device__ int   g_counts[Nn];
__device__ int   g_fill[Nn];
__device__ int   g_rowptr[Nn + 1];
__device__ int   g_dst[Ee];
__device__ int   g_blksums[128];

// ---------------- CSR construction ----------------
__global__ void zero_kernel() {
    int i = blockIdx.x * blockDim.x + threadIdx.x;
    if (i < Nn) { g_counts[i] = 0; g_fill[i] = 0; }
}

__global__ void count_kernel(const int* __restrict__ src) {
    int e = blockIdx.x * blockDim.x + threadIdx.x;
    if (e < Ee) atomicAdd(&g_counts[src[e]], 1);
}

__global__ void scan_block_kernel() {
    __shared__ int sh[1024];
    int i = blockIdx.x * 1024 + threadIdx.x;
    int v = (i < Nn) ? g_counts[i] : 0;
    sh[threadIdx.x] = v;
    __syncthreads();
    #pragma unroll
    for (int off = 1; off < 1024; off <<= 1) {
        int t = (threadIdx.x >= off) ? sh[threadIdx.x - off] : 0;
        __syncthreads();
        sh[threadIdx.x] += t;
        __syncthreads();
    }
    if (i < Nn) g_rowptr[i] = sh[threadIdx.x] - v;   // exclusive within block
    if (threadIdx.x == 1023) g_blksums[blockIdx.x] = sh[1023];
}

__global__ void scan_top_kernel() {
    if (threadIdx.x == 0 && blockIdx.x == 0) {
        int s = 0;
        for (int i = 0; i < NB_SCAN; i++) { int v = g_blksums[i]; g_blksums[i] = s; s += v; }
    }
}

__global__ void scan_add_kernel() {
    int i = blockIdx.x * blockDim.x + threadIdx.x;
    if (i < Nn) g_rowptr[i] += g_blksums[i >> 10];
    if (i == 0) g_rowptr[Nn] = Ee;
}

__global__ void scatter_kernel(const int* __restrict__ src, const int* __restrict__ dst) {
    int e = blockIdx.x * blockDim.x + threadIdx.x;
    if (e < Ee) {
        int s = src[e];
        int pos = g_rowptr[s] + atomicAdd(&g_fill[s], 1);
        g_dst[pos] = dst[e];
    }
}

// ---------------- weight repack: Wcat[i][h*64+j] = W_heads[h][i][j] ----------------
__global__ void repack_kernel(const float* __restrict__ W_heads) {
    int t = blockIdx.x * blockDim.x + threadIdx.x;
    if (t >= INF * F1) return;
    int i = t / F1;
    int c = t - i * F1;
    int h = c >> 6;
    int j = c & 63;
    g_Wcat[t] = W_heads[(h * INF + i) * HIDF + j];
}

// ---------------- generic tiled fp32 GEMM: C[n,M] = A[n,K] @ B[K,M] (+bias) ----------------
// BM=BN=64, BK=16, 256 threads, 4x4 microtile
__global__ void gemm_kernel(const float* __restrict__ A, const float* __restrict__ B,
                            const float* __restrict__ bias, float* __restrict__ C,
                            int n, int K, int M) {
    __shared__ float As[16][68];   // [k][m], padded, float4-aligned (68 % 4 == 0)
    __shared__ float Bs[16][64];   // [k][n]
    int t  = threadIdx.x;
    int tx = t & 15, ty = t >> 4;
    int bm = blockIdx.y * 64;
    int bn = blockIdx.x * 64;

    int ar = t >> 2;            // 0..63  (A tile row)
    int ac = (t & 3) * 4;       // 0..12  (A tile col, float4)
    int br = t >> 4;            // 0..15  (B tile row)
    int bc = (t & 15) * 4;      // 0..60  (B tile col, float4)

    float acc[4][4] = {};
    int arow = bm + ar;
    bool arow_ok = arow < n;
    const float* Ap = A + (size_t)arow * K + ac;

    for (int k0 = 0; k0 < K; k0 += 16) {
        float4 av = arow_ok ? *(const float4*)(Ap + k0) : make_float4(0.f, 0.f, 0.f, 0.f);
        float4 bv = *(const float4*)(B + (size_t)(k0 + br) * M + bn + bc);
        __syncthreads();
        As[ac + 0][ar] = av.x; As[ac + 1][ar] = av.y;
        As[ac + 2][ar] = av.z; As[ac + 3][ar] = av.w;
        *(float4*)&Bs[br][bc] = bv;
        __syncthreads();
        #pragma unroll
        for (int kk = 0; kk < 16; kk++) {
            float a4[4], b4[4];
            *(float4*)a4 = *(const float4*)&As[kk][ty * 4];
            *(float4*)b4 = *(const float4*)&Bs[kk][tx * 4];
            #pragma unroll
            for (int i = 0; i < 4; i++)
                #pragma unroll
                for (int j = 0; j < 4; j++)
                    acc[i][j] += a4[i] * b4[j];
        }
    }

    int col = bn + tx * 4;
    float bsv[4] = {0.f, 0.f, 0.f, 0.f};
    if (bias) { *(float4*)bsv = *(const float4*)(bias + col); }
    #pragma unroll
    for (int i = 0; i < 4; i++) {
        int row = bm + ty * 4 + i;
        if (row < n) {
            float4 o;
            o.x = acc[i][0] + bsv[0];
            o.y = acc[i][1] + bsv[1];
            o.z = acc[i][2] + bsv[2];
            o.w = acc[i][3] + bsv[3];
            *(float4*)(C + (size_t)row * M + col) = o;
        }
    }
}

// ---------------- per-node scores layer 1: block per node, warp per head ----------------
__global__ void s1_kernel(const float* __restrict__ a_heads) {
    int node = blockIdx.x;
    int h    = threadIdx.x >> 5;
    int lane = threadIdx.x & 31;
    const float* base = g_h1 + (size_t)node * F1 + h * 64;
    const float* ah   = a_heads + h * 128;
    float v0 = base[lane], v1 = base[lane + 32];
    float ssrc = v0 * ah[lane]      + v1 * ah[lane + 32];
    float sdst = v0 * ah[64 + lane] + v1 * ah[96 + lane];
    #pragma unroll
    for (int off = 16; off; off >>= 1) {
        ssrc += __shfl_xor_sync(0xffffffffu, ssrc, off);
        sdst += __shfl_xor_sync(0xffffffffu, sdst, off);
    }
    if (lane == 0) {
        g_ssrc1[node * NH + h] = ssrc;
        g_sdst1[node * NH + h] = sdst;
    }
}

// ---------------- layer-1 aggregation: warp per node ----------------
__global__ void agg1_kernel() {
    int node = (blockIdx.x * blockDim.x + threadIdx.x) >> 5;
    if (node >= Nn) return;
    int lane = threadIdx.x & 31;
    int hl   = lane & 7;        // head whose weight this lane computes
    int hsel = lane >> 4;       // 0/1: which head within each 128-col chunk

    float ssrc = g_ssrc1[node * NH + hl];
    int beg = g_rowptr[node], end = g_rowptr[node + 1];

    float4 acc[4];
    float  rs[4];
    #pragma unroll
    for (int k = 0; k < 4; k++) { acc[k] = make_float4(0.f,0.f,0.f,0.f); rs[k] = 0.f; }

    for (int j = beg; j < end; j++) {
        int d = g_dst[j];
        float sc = ssrc + g_sdst1[d * NH + hl];
        float lr = sc > 0.f ? sc : ALPHA * sc;
        float w8 = __expf(-lr);
        const float4* hp = (const float4*)(g_h1 + (size_t)d * F1);
        #pragma unroll
        for (int k = 0; k < 4; k++) {
            float w = __shfl_sync(0xffffffffu, w8, 2 * k + hsel);
            float4 v = hp[k * 32 + lane];
            acc[k].x += w * v.x; acc[k].y += w * v.y;
            acc[k].z += w * v.z; acc[k].w += w * v.w;
            rs[k] += w;
        }
    }

    float* outp = g_out1 + (size_t)node * F1;
    #pragma unroll
    for (int k = 0; k < 4; k++) {
        float inv = 1.f / (rs[k] + 1e-16f);
        float4 o;
        o.x = acc[k].x * inv; o.y = acc[k].y * inv;
        o.z = acc[k].z * inv; o.w = acc[k].w * inv;
        // ELU
        o.x = o.x > 0.f ? o.x : expm1f(o.x);
        o.y = o.y > 0.f ? o.y : expm1f(o.y);
        o.z = o.z > 0.f ? o.z : expm1f(o.z);
        o.w = o.w > 0.f ? o.w : expm1f(o.w);
        *(float4*)(outp + k * 128 + lane * 4) = o;
    }
}

// ---------------- per-node scores layer 2: warp per node ----------------
__global__ void s2_kernel(const float* __restrict__ a_end) {
    int node = (blockIdx.x * blockDim.x + threadIdx.x) >> 5;
    if (node >= Nn) return;
    int lane = threadIdx.x & 31;
    const float* base = g_h2 + (size_t)node * OUTF;
    float v0 = base[lane], v1 = base[lane + 32];
    float ssrc = v0 * a_end[lane]      + v1 * a_end[lane + 32];
    float sdst = v0 * a_end[64 + lane] + v1 * a_end[96 + lane];
    #pragma unroll
    for (int off = 16; off; off >>= 1) {
        ssrc += __shfl_xor_sync(0xffffffffu, ssrc, off);
        sdst += __shfl_xor_sync(0xffffffffu, sdst, off);
    }
    if (lane == 0) { g_ssrc2[node] = ssrc; g_sdst2[node] = sdst; }
}

// ---------------- layer-2 aggregation + softmax: warp per node ----------------
__global__ void agg2_kernel(float* __restrict__ out) {
    int node = (blockIdx.x * blockDim.x + threadIdx.x) >> 5;
    if (node >= Nn) return;
    int lane = threadIdx.x & 31;

    float ss = g_ssrc2[node];
    int beg = g_rowptr[node], end = g_rowptr[node + 1];
    float a0 = 0.f, a1 = 0.f, rs = 0.f;
    for (int j = beg; j < end; j++) {
        int d = g_dst[j];
        float sc = ss + g_sdst2[d];
        float lr = sc > 0.f ? sc : ALPHA * sc;
        float w = __expf(-lr);
        const float* hp = g_h2 + (size_t)d * OUTF;
        a0 += w * hp[lane];
        a1 += w * hp[lane + 32];
        rs += w;
    }
    float inv = 1.f / (rs + 1e-16f);
    float v0 = a0 * inv, v1 = a1 * inv;

    // softmax over the 64 outputs (2 per lane)
    float m = fmaxf(v0, v1);
    #pragma unroll
    for (int off = 16; off; off >>= 1) m = fmaxf(m, __shfl_xor_sync(0xffffffffu, m, off));
    float e0 = __expf(v0 - m), e1 = __expf(v1 - m);
    float s = e0 + e1;
    #pragma unroll
    for (int off = 16; off; off >>= 1) s += __shfl_xor_sync(0xffffffffu, s, off);
    float invs = 1.f / s;
    out[(size_t)node * OUTF + lane]      = e0 * invs;
    out[(size_t)node * OUTF + lane + 32] = e1 * invs;
}

// ---------------- launch ----------------
extern "C" void kernel_launch(void* const* d_in, const int* in_sizes, int n_in,
                              void* d_out, int out_size) {
    const float* x       = (const float*)d_in[0];
    const int*   edges   = (const int*)  d_in[1];
    const float* W0      = (const float*)d_in[2];
    const float* b0      = (const float*)d_in[3];
    const float* W_heads = (const float*)d_in[4];
    const float* a_heads = (const float*)d_in[5];
    const float* W_end   = (const float*)d_in[6];
    const float* a_end   = (const float*)d_in[7];
    float* out = (float*)d_out;
    const int* src = edges;
    const int* dst = edges + Ee;

    float *p_xp, *p_h1, *p_out1, *p_h2, *p_Wcat;
    cudaGetSymbolAddress((void**)&p_xp,   g_xp);
    cudaGetSymbolAddress((void**)&p_h1,   g_h1);
    cudaGetSymbolAddress((void**)&p_out1, g_out1);
    cudaGetSymbolAddress((void**)&p_h2,   g_h2);
    cudaGetSymbolAddress((void**)&p_Wcat, g_Wcat);

    // CSR build
    zero_kernel<<<(Nn + 255) / 256, 256>>>();
    count_kernel<<<(Ee + 255) / 256, 256>>>(src);
    scan_block_kernel<<<NB_SCAN, 1024>>>();
    scan_top_kernel<<<1, 32>>>();
    scan_add_kernel<<<(Nn + 255) / 256, 256>>>();
    scatter_kernel<<<(Ee + 255) / 256, 256>>>(src, dst);

    // weight repack (independent of CSR, cheap)
    repack_kernel<<<(INF * F1 + 255) / 256, 256>>>(W_heads);

    // xp = x @ W0 + b0
    {
        dim3 grid(INF / 64, (Nn + 63) / 64);
        gemm_kernel<<<grid, 256>>>(x, W0, b0, p_xp, Nn, INF, INF);
    }
    // h1 = xp @ Wcat   (all 8 heads fused, [N,512])
    {
        dim3 grid(F1 / 64, (Nn + 63) / 64);
        gemm_kernel<<<grid, 256>>>(p_xp, p_Wcat, nullptr, p_h1, Nn, INF, F1);
    }
    // per-node scores, layer 1
    s1_kernel<<<Nn, 256>>>(a_heads);
    // layer-1 aggregation + ELU -> out1 [N,512]
    agg1_kernel<<<(Nn + 7) / 8, 256>>>();

    // h2 = out1 @ W_end  [N,64]
    {
        dim3 grid(OUTF / 64, (Nn + 63) / 64);
        gemm_kernel<<<grid, 256>>>(p_out1, W_end, nullptr, p_h2, Nn, F1, OUTF);
    }
    // per-node scores, layer 2
    s2_kernel<<<(Nn + 7) / 8, 256>>>(a_end);
    // layer-2 aggregation + softmax -> output
    agg2_kernel<<<(Nn + 7) / 8, 256>>>(out);
}

// round 5
// speedup vs baseline: 1.2115x; 1.2059x over previous
#include <cuda_runtime.h>
#include <cuda_fp16.h>
#include <math.h>

// Problem constants (fixed by the reference)
#define Nn   100000
#define Ee   1600000
#define INF  128
#define HIDF 64
#define NH   8
#define F1   512      // NH*HIDF
#define OUTF 64
#define ALPHA 0.2f
#define NB_SCAN ((Nn + 1023) / 1024)   // 98

// ---------------- device scratch (no allocations allowed) ----------------
__device__ float  g_xp[Nn * INF];                 // 51.2 MB
__device__ __half g_h1[(size_t)Nn * F1];          // 102.4 MB (fits ~L2!)
__device__ __half g_out1[(size_t)Nn * F1];        // 102.4 MB
__device__ float  g_h2[Nn * OUTF];                // 25.6 MB
__device__ float  g_Wcat[INF * F1];               // repacked head weights
__device__ float  g_ssrc1[Nn * NH];
__device__ float  g_sdst1[Nn * NH];
__device__ float  g_ssrc2[Nn];
__device__ float  g_sdst2[Nn];
__device__ int    g_counts[Nn];
__device__ int    g_fill[Nn];
__device__ int    g_rowptr[Nn + 1];
__device__ int    g_dst[Ee];
__device__ int    g_blksums[128];

// ---------------- fp16 helpers ----------------
__device__ __forceinline__ void store_half4(__half* p, float4 v) {
    __half2 a = __floats2half2_rn(v.x, v.y);
    __half2 b = __floats2half2_rn(v.z, v.w);
    uint2 u;
    u.x = *(unsigned int*)&a;
    u.y = *(unsigned int*)&b;
    *(uint2*)p = u;
}
__device__ __forceinline__ float4 load_half4(const __half* p) {
    uint2 u = *(const uint2*)p;
    __half2 a = *(__half2*)&u.x;
    __half2 b = *(__half2*)&u.y;
    float2 fa = __half22float2(a), fb = __half22float2(b);
    return make_float4(fa.x, fa.y, fb.x, fb.y);
}

// ---------------- CSR construction ----------------
__global__ void zero_kernel() {
    int i = blockIdx.x * blockDim.x + threadIdx.x;
    if (i < Nn) { g_counts[i] = 0; g_fill[i] = 0; }
}

__global__ void count_kernel(const int* __restrict__ src) {
    int e = blockIdx.x * blockDim.x + threadIdx.x;
    if (e < Ee) atomicAdd(&g_counts[src[e]], 1);
}

__global__ void scan_block_kernel() {
    __shared__ int sh[1024];
    int i = blockIdx.x * 1024 + threadIdx.x;
    int v = (i < Nn) ? g_counts[i] : 0;
    sh[threadIdx.x] = v;
    __syncthreads();
    #pragma unroll
    for (int off = 1; off < 1024; off <<= 1) {
        int t = (threadIdx.x >= off) ? sh[threadIdx.x - off] : 0;
        __syncthreads();
        sh[threadIdx.x] += t;
        __syncthreads();
    }
    if (i < Nn) g_rowptr[i] = sh[threadIdx.x] - v;   // exclusive within block
    if (threadIdx.x == 1023) g_blksums[blockIdx.x] = sh[1023];
}

__global__ void scan_top_kernel() {
    if (threadIdx.x == 0 && blockIdx.x == 0) {
        int s = 0;
        for (int i = 0; i < NB_SCAN; i++) { int v = g_blksums[i]; g_blksums[i] = s; s += v; }
    }
}

__global__ void scan_add_kernel() {
    int i = blockIdx.x * blockDim.x + threadIdx.x;
    if (i < Nn) g_rowptr[i] += g_blksums[i >> 10];
    if (i == 0) g_rowptr[Nn] = Ee;
}

__global__ void scatter_kernel(const int* __restrict__ src, const int* __restrict__ dst) {
    int e = blockIdx.x * blockDim.x + threadIdx.x;
    if (e < Ee) {
        int s = src[e];
        int pos = g_rowptr[s] + atomicAdd(&g_fill[s], 1);
        g_dst[pos] = dst[e];
    }
}

// ---------------- weight repack: Wcat[i][h*64+j] = W_heads[h][i][j] ----------------
__global__ void repack_kernel(const float* __restrict__ W_heads) {
    int t = blockIdx.x * blockDim.x + threadIdx.x;
    if (t >= INF * F1) return;
    int i = t / F1;
    int c = t - i * F1;
    int h = c >> 6;
    int j = c & 63;
    g_Wcat[t] = W_heads[(h * INF + i) * HIDF + j];
}

// ---------------- GEMM1: fp32 in, fp32 out (+bias) ----------------
// BM=BN=64, BK=16, 256 threads, 4x4 microtile
__global__ void gemm_kernel(const float* __restrict__ A, const float* __restrict__ B,
                            const float* __restrict__ bias, float* __restrict__ C,
                            int n, int K, int M) {
    __shared__ float As[16][68];
    __shared__ float Bs[16][64];
    int t  = threadIdx.x;
    int tx = t & 15, ty = t >> 4;
    int bm = blockIdx.y * 64;
    int bn = blockIdx.x * 64;

    int ar = t >> 2;
    int ac = (t & 3) * 4;
    int br = t >> 4;
    int bc = (t & 15) * 4;

    float acc[4][4] = {};
    int arow = bm + ar;
    bool arow_ok = arow < n;
    const float* Ap = A + (size_t)arow * K + ac;

    for (int k0 = 0; k0 < K; k0 += 16) {
        float4 av = arow_ok ? *(const float4*)(Ap + k0) : make_float4(0.f, 0.f, 0.f, 0.f);
        float4 bv = *(const float4*)(B + (size_t)(k0 + br) * M + bn + bc);
        __syncthreads();
        As[ac + 0][ar] = av.x; As[ac + 1][ar] = av.y;
        As[ac + 2][ar] = av.z; As[ac + 3][ar] = av.w;
        *(float4*)&Bs[br][bc] = bv;
        __syncthreads();
        #pragma unroll
        for (int kk = 0; kk < 16; kk++) {
            float a4[4], b4[4];
            *(float4*)a4 = *(const float4*)&As[kk][ty * 4];
            *(float4*)b4 = *(const float4*)&Bs[kk][tx * 4];
            #pragma unroll
            for (int i = 0; i < 4; i++)
                #pragma unroll
                for (int j = 0; j < 4; j++)
                    acc[i][j] += a4[i] * b4[j];
        }
    }

    int col = bn + tx * 4;
    float bsv[4] = {0.f, 0.f, 0.f, 0.f};
    if (bias) { *(float4*)bsv = *(const float4*)(bias + col); }
    #pragma unroll
    for (int i = 0; i < 4; i++) {
        int row = bm + ty * 4 + i;
        if (row < n) {
            float4 o;
            o.x = acc[i][0] + bsv[0];
            o.y = acc[i][1] + bsv[1];
            o.z = acc[i][2] + bsv[2];
            o.w = acc[i][3] + bsv[3];
            *(float4*)(C + (size_t)row * M + col) = o;
        }
    }
}

// ---------------- GEMM2: fp32 A/B -> half C, fused per-head score epilogue ----------------
// Each 64-col tile is exactly one head (blockIdx.x = head). Scores computed from
// the fp32 accumulators (full precision), output quantized to fp16.
__global__ void gemm2_kernel(const float* __restrict__ A, const float* __restrict__ B,
                             __half* __restrict__ C, const float* __restrict__ a_heads,
                             int n) {
    const int K = INF, M = F1;
    __shared__ float As[16][68];
    __shared__ float Bs[16][64];
    int t  = threadIdx.x;
    int tx = t & 15, ty = t >> 4;
    int bm = blockIdx.y * 64;
    int bn = blockIdx.x * 64;          // head h = blockIdx.x
    int h  = blockIdx.x;

    int ar = t >> 2;
    int ac = (t & 3) * 4;
    int br = t >> 4;
    int bc = (t & 15) * 4;

    float acc[4][4] = {};
    int arow = bm + ar;
    bool arow_ok = arow < n;
    const float* Ap = A + (size_t)arow * K + ac;

    for (int k0 = 0; k0 < K; k0 += 16) {
        float4 av = arow_ok ? *(const float4*)(Ap + k0) : make_float4(0.f, 0.f, 0.f, 0.f);
        float4 bv = *(const float4*)(B + (size_t)(k0 + br) * M + bn + bc);
        __syncthreads();
        As[ac + 0][ar] = av.x; As[ac + 1][ar] = av.y;
        As[ac + 2][ar] = av.z; As[ac + 3][ar] = av.w;
        *(float4*)&Bs[br][bc] = bv;
        __syncthreads();
        #pragma unroll
        for (int kk = 0; kk < 16; kk++) {
            float a4[4], b4[4];
            *(float4*)a4 = *(const float4*)&As[kk][ty * 4];
            *(float4*)b4 = *(const float4*)&Bs[kk][tx * 4];
            #pragma unroll
            for (int i = 0; i < 4; i++)
                #pragma unroll
                for (int j = 0; j < 4; j++)
                    acc[i][j] += a4[i] * b4[j];
        }
    }

    int col = bn + tx * 4;

    // attention-vector slices for this head and this thread's 4 columns
    float a_s[4], a_d[4];
    *(float4*)a_s = *(const float4*)(a_heads + h * 128 + tx * 4);
    *(float4*)a_d = *(const float4*)(a_heads + h * 128 + 64 + tx * 4);

    #pragma unroll
    for (int i = 0; i < 4; i++) {
        int row = bm + ty * 4 + i;
        // half store of the tile
        if (row < n) {
            float4 o = make_float4(acc[i][0], acc[i][1], acc[i][2], acc[i][3]);
            store_half4(C + (size_t)row * M + col, o);
        }
        // fused score partials: reduce over the 16 tx lanes (one half-warp)
        float ps = acc[i][0] * a_s[0] + acc[i][1] * a_s[1]
                 + acc[i][2] * a_s[2] + acc[i][3] * a_s[3];
        float pd = acc[i][0] * a_d[0] + acc[i][1] * a_d[1]
                 + acc[i][2] * a_d[2] + acc[i][3] * a_d[3];
        #pragma unroll
        for (int off = 8; off; off >>= 1) {
            ps += __shfl_xor_sync(0xffffffffu, ps, off, 16);
            pd += __shfl_xor_sync(0xffffffffu, pd, off, 16);
        }
        if (tx == 0 && row < n) {
            g_ssrc1[row * NH + h] = ps;
            g_sdst1[row * NH + h] = pd;
        }
    }
}

// ---------------- GEMM3: half A, fp32 B -> fp32 C ----------------
__global__ void gemm_ah_kernel(const __half* __restrict__ A, const float* __restrict__ B,
                               float* __restrict__ C, int n, int K, int M) {
    __shared__ float As[16][68];
    __shared__ float Bs[16][64];
    int t  = threadIdx.x;
    int tx = t & 15, ty = t >> 4;
    int bm = blockIdx.y * 64;
    int bn = blockIdx.x * 64;

    int ar = t >> 2;
    int ac = (t & 3) * 4;
    int br = t >> 4;
    int bc = (t & 15) * 4;

    float acc[4][4] = {};
    int arow = bm + ar;
    bool arow_ok = arow < n;
    const __half* Ap = A + (size_t)arow * K + ac;

    for (int k0 = 0; k0 < K; k0 += 16) {
        float4 av = arow_ok ? load_half4(Ap + k0) : make_float4(0.f, 0.f, 0.f, 0.f);
        float4 bv = *(const float4*)(B + (size_t)(k0 + br) * M + bn + bc);
        __syncthreads();
        As[ac + 0][ar] = av.x; As[ac + 1][ar] = av.y;
        As[ac + 2][ar] = av.z; As[ac + 3][ar] = av.w;
        *(float4*)&Bs[br][bc] = bv;
        __syncthreads();
        #pragma unroll
        for (int kk = 0; kk < 16; kk++) {
            float a4[4], b4[4];
            *(float4*)a4 = *(const float4*)&As[kk][ty * 4];
            *(float4*)b4 = *(const float4*)&Bs[kk][tx * 4];
            #pragma unroll
            for (int i = 0; i < 4; i++)
                #pragma unroll
                for (int j = 0; j < 4; j++)
                    acc[i][j] += a4[i] * b4[j];
        }
    }

    int col = bn + tx * 4;
    #pragma unroll
    for (int i = 0; i < 4; i++) {
        int row = bm + ty * 4 + i;
        if (row < n) {
            float4 o = make_float4(acc[i][0], acc[i][1], acc[i][2], acc[i][3]);
            *(float4*)(C + (size_t)row * M + col) = o;
        }
    }
}

// ---------------- layer-1 aggregation: warp per node (fp16 gather, fp32 accum) ----------------
__global__ void agg1_kernel() {
    int node = (blockIdx.x * blockDim.x + threadIdx.x) >> 5;
    if (node >= Nn) return;
    int lane = threadIdx.x & 31;
    int hl   = lane & 7;        // head whose weight this lane computes
    int hsel = lane >> 4;       // 0/1: which head within each 128-col chunk

    float ssrc = g_ssrc1[node * NH + hl];
    int beg = g_rowptr[node], end = g_rowptr[node + 1];

    float4 acc[4];
    float  rs[4];
    #pragma unroll
    for (int k = 0; k < 4; k++) { acc[k] = make_float4(0.f,0.f,0.f,0.f); rs[k] = 0.f; }

    for (int j = beg; j < end; j++) {
        int d = g_dst[j];
        float sc = ssrc + g_sdst1[d * NH + hl];
        float lr = sc > 0.f ? sc : ALPHA * sc;
        float w8 = __expf(-lr);
        const __half* hp = g_h1 + (size_t)d * F1;
        #pragma unroll
        for (int k = 0; k < 4; k++) {
            float w = __shfl_sync(0xffffffffu, w8, 2 * k + hsel);
            float4 v = load_half4(hp + k * 128 + lane * 4);
            acc[k].x += w * v.x; acc[k].y += w * v.y;
            acc[k].z += w * v.z; acc[k].w += w * v.w;
            rs[k] += w;
        }
    }

    __half* outp = g_out1 + (size_t)node * F1;
    #pragma unroll
    for (int k = 0; k < 4; k++) {
        float inv = 1.f / (rs[k] + 1e-16f);
        float4 o;
        o.x = acc[k].x * inv; o.y = acc[k].y * inv;
        o.z = acc[k].z * inv; o.w = acc[k].w * inv;
        // ELU
        o.x = o.x > 0.f ? o.x : expm1f(o.x);
        o.y = o.y > 0.f ? o.y : expm1f(o.y);
        o.z = o.z > 0.f ? o.z : expm1f(o.z);
        o.w = o.w > 0.f ? o.w : expm1f(o.w);
        store_half4(outp + k * 128 + lane * 4, o);
    }
}

// ---------------- per-node scores layer 2: warp per node ----------------
__global__ void s2_kernel(const float* __restrict__ a_end) {
    int node = (blockIdx.x * blockDim.x + threadIdx.x) >> 5;
    if (node >= Nn) return;
    int lane = threadIdx.x & 31;
    const float* base = g_h2 + (size_t)node * OUTF;
    float v0 = base[lane], v1 = base[lane + 32];
    float ssrc = v0 * a_end[lane]      + v1 * a_end[lane + 32];
    float sdst = v0 * a_end[64 + lane] + v1 * a_end[96 + lane];
    #pragma unroll
    for (int off = 16; off; off >>= 1) {
        ssrc += __shfl_xor_sync(0xffffffffu, ssrc, off);
        sdst += __shfl_xor_sync(0xffffffffu, sdst, off);
    }
    if (lane == 0) { g_ssrc2[node] = ssrc; g_sdst2[node] = sdst; }
}

// ---------------- layer-2 aggregation + softmax: warp per node ----------------
__global__ void agg2_kernel(float* __restrict__ out) {
    int node = (blockIdx.x * blockDim.x + threadIdx.x) >> 5;
    if (node >= Nn) return;
    int lane = threadIdx.x & 31;

    float ss = g_ssrc2[node];
    int beg = g_rowptr[node], end = g_rowptr[node + 1];
    float a0 = 0.f, a1 = 0.f, rs = 0.f;
    for (int j = beg; j < end; j++) {
        int d = g_dst[j];
        float sc = ss + g_sdst2[d];
        float lr = sc > 0.f ? sc : ALPHA * sc;
        float w = __expf(-lr);
        const float* hp = g_h2 + (size_t)d * OUTF;
        a0 += w * hp[lane];
        a1 += w * hp[lane + 32];
        rs += w;
    }
    float inv = 1.f / (rs + 1e-16f);
    float v0 = a0 * inv, v1 = a1 * inv;

    // softmax over the 64 outputs (2 per lane)
    float m = fmaxf(v0, v1);
    #pragma unroll
    for (int off = 16; off; off >>= 1) m = fmaxf(m, __shfl_xor_sync(0xffffffffu, m, off));
    float e0 = __expf(v0 - m), e1 = __expf(v1 - m);
    float s = e0 + e1;
    #pragma unroll
    for (int off = 16; off; off >>= 1) s += __shfl_xor_sync(0xffffffffu, s, off);
    float invs = 1.f / s;
    out[(size_t)node * OUTF + lane]      = e0 * invs;
    out[(size_t)node * OUTF + lane + 32] = e1 * invs;
}

// ---------------- launch ----------------
extern "C" void kernel_launch(void* const* d_in, const int* in_sizes, int n_in,
                              void* d_out, int out_size) {
    const float* x       = (const float*)d_in[0];
    const int*   edges   = (const int*)  d_in[1];
    const float* W0      = (const float*)d_in[2];
    const float* b0      = (const float*)d_in[3];
    const float* W_heads = (const float*)d_in[4];
    const float* a_heads = (const float*)d_in[5];
    const float* W_end   = (const float*)d_in[6];
    const float* a_end   = (const float*)d_in[7];
    float* out = (float*)d_out;
    const int* src = edges;
    const int* dst = edges + Ee;

    float  *p_xp, *p_h2, *p_Wcat;
    __half *p_h1, *p_out1;
    cudaGetSymbolAddress((void**)&p_xp,   g_xp);
    cudaGetSymbolAddress((void**)&p_h1,   g_h1);
    cudaGetSymbolAddress((void**)&p_out1, g_out1);
    cudaGetSymbolAddress((void**)&p_h2,   g_h2);
    cudaGetSymbolAddress((void**)&p_Wcat, g_Wcat);

    // CSR build
    zero_kernel<<<(Nn + 255) / 256, 256>>>();
    count_kernel<<<(Ee + 255) / 256, 256>>>(src);
    scan_block_kernel<<<NB_SCAN, 1024>>>();
    scan_top_kernel<<<1, 32>>>();
    scan_add_kernel<<<(Nn + 255) / 256, 256>>>();
    scatter_kernel<<<(Ee + 255) / 256, 256>>>(src, dst);

    // weight repack (independent of CSR, cheap)
    repack_kernel<<<(INF * F1 + 255) / 256, 256>>>(W_heads);

    // xp = x @ W0 + b0
    {
        dim3 grid(INF / 64, (Nn + 63) / 64);
        gemm_kernel<<<grid, 256>>>(x, W0, b0, p_xp, Nn, INF, INF);
    }
    // h1 = xp @ Wcat (half output) + fused per-head scores
    {
        dim3 grid(F1 / 64, (Nn + 63) / 64);
        gemm2_kernel<<<grid, 256>>>(p_xp, p_Wcat, p_h1, a_heads, Nn);
    }
    // layer-1 aggregation + ELU -> out1 [N,512] (fp16)
    agg1_kernel<<<(Nn + 7) / 8, 256>>>();

    // h2 = out1 @ W_end  [N,64] (half A)
    {
        dim3 grid(OUTF / 64, (Nn + 63) / 64);
        gemm_ah_kernel<<<grid, 256>>>(p_out1, W_end, p_h2, Nn, F1, OUTF);
    }
    // per-node scores, layer 2
    s2_kernel<<<(Nn + 7) / 8, 256>>>(a_end);
    // layer-2 aggregation + softmax -> output
    agg2_kernel<<<(Nn + 7) / 8, 256>>>(out);
}

// round 7
// speedup vs baseline: 1.9191x; 1.5840x over previous
#include <cuda_runtime.h>
#include <cuda_fp16.h>
#include <math.h>
#include <stdint.h>

// Problem constants (fixed by the reference)
#define Nn   100000
#define Ee   1600000
#define INF  128
#define HIDF 64
#define NH   8
#define F1   512      // NH*HIDF
#define OUTF 64
#define ALPHA 0.2f
#define NB_SCAN ((Nn + 1023) / 1024)   // 98

// ---------------- device scratch (no allocations allowed) ----------------
__device__ __half g_x_h[(size_t)Nn * INF];        // 25.6 MB
__device__ __half g_xp_h[(size_t)Nn * INF];       // 25.6 MB
__device__ __half g_h1[(size_t)Nn * F1];          // 102.4 MB (~fits L2)
__device__ __half g_out1[(size_t)Nn * F1];        // 102.4 MB
__device__ float  g_h2[Nn * OUTF];                // 25.6 MB
__device__ __half g_W0h[INF * INF];
__device__ __half g_Wcat_h[INF * F1];             // repacked head weights (fp16)
__device__ __half g_Wend_h[F1 * OUTF];
__device__ float  g_ssrc1[Nn * NH];
__device__ float  g_sdst1[Nn * NH];
__device__ float  g_ssrc2[Nn];
__device__ float  g_sdst2[Nn];
__device__ int    g_counts[Nn];
__device__ int    g_fill[Nn];
__device__ int    g_rowptr[Nn + 1];
__device__ int    g_dst[Ee];
__device__ int    g_blksums[128];

// ---------------- fp16 helpers ----------------
__device__ __forceinline__ void store_half4(__half* p, float4 v) {
    __half2 a = __floats2half2_rn(v.x, v.y);
    __half2 b = __floats2half2_rn(v.z, v.w);
    uint2 u;
    u.x = *(unsigned int*)&a;
    u.y = *(unsigned int*)&b;
    *(uint2*)p = u;
}
__device__ __forceinline__ float4 load_half4(const __half* p) {
    uint2 u = *(const uint2*)p;
    __half2 a = *(__half2*)&u.x;
    __half2 b = *(__half2*)&u.y;
    float2 fa = __half22float2(a), fb = __half22float2(b);
    return make_float4(fa.x, fa.y, fb.x, fb.y);
}
__device__ __forceinline__ unsigned int smem_u32(const void* p) {
    return (unsigned int)__cvta_generic_to_shared(p);
}

// ---------------- CSR construction ----------------
__global__ void zero_kernel() {
    int i = blockIdx.x * blockDim.x + threadIdx.x;
    if (i < Nn) { g_counts[i] = 0; g_fill[i] = 0; }
}

__global__ void count_kernel(const int* __restrict__ src) {
    int e = blockIdx.x * blockDim.x + threadIdx.x;
    if (e < Ee) atomicAdd(&g_counts[src[e]], 1);
}

__global__ void scan_block_kernel() {
    __shared__ int sh[1024];
    int i = blockIdx.x * 1024 + threadIdx.x;
    int v = (i < Nn) ? g_counts[i] : 0;
    sh[threadIdx.x] = v;
    __syncthreads();
    #pragma unroll
    for (int off = 1; off < 1024; off <<= 1) {
        int t = (threadIdx.x >= off) ? sh[threadIdx.x - off] : 0;
        __syncthreads();
        sh[threadIdx.x] += t;
        __syncthreads();
    }
    if (i < Nn) g_rowptr[i] = sh[threadIdx.x] - v;   // exclusive within block
    if (threadIdx.x == 1023) g_blksums[blockIdx.x] = sh[1023];
}

__global__ void scan_top_kernel() {
    if (threadIdx.x == 0 && blockIdx.x == 0) {
        int s = 0;
        for (int i = 0; i < NB_SCAN; i++) { int v = g_blksums[i]; g_blksums[i] = s; s += v; }
    }
}

__global__ void scan_add_kernel() {
    int i = blockIdx.x * blockDim.x + threadIdx.x;
    if (i < Nn) g_rowptr[i] += g_blksums[i >> 10];
    if (i == 0) g_rowptr[Nn] = Ee;
}

__global__ void scatter_kernel(const int* __restrict__ src, const int* __restrict__ dst) {
    int e = blockIdx.x * blockDim.x + threadIdx.x;
    if (e < Ee) {
        int s = src[e];
        int pos = g_rowptr[s] + atomicAdd(&g_fill[s], 1);
        g_dst[pos] = dst[e];
    }
}

// ---------------- conversions ----------------
__global__ void f2h_kernel(const float* __restrict__ in, __half* __restrict__ out, int nElem) {
    int i = (blockIdx.x * blockDim.x + threadIdx.x) * 4;
    if (i < nElem) {
        float4 v = *(const float4*)(in + i);
        store_half4(out + i, v);
    }
}

// Wcat_h[i][h*64+j] = W_heads[h][i][j]   (fp16)
__global__ void repack_kernel(const float* __restrict__ W_heads) {
    int t = blockIdx.x * blockDim.x + threadIdx.x;
    if (t >= INF * F1) return;
    int i = t / F1;
    int c = t - i * F1;
    int h = c >> 6;
    int j = c & 63;
    g_Wcat_h[t] = __float2half(W_heads[(h * INF + i) * HIDF + j]);
}

// ---------------- tensor-core GEMM: C[n,M] = A[n,K] @ B[K,M] ----------------
// fp16 A/B, fp32 accumulate. BM=128, BN=64, BK=32, 256 threads (8 warps, 4x2).
// K % 32 == 0, M % 64 == 0 (true for all call sites).
template<bool HALF_OUT, bool BIAS>
__global__ void mma_gemm_kernel(const __half* __restrict__ A, const __half* __restrict__ B,
                                const float* __restrict__ bias, void* __restrict__ Cv,
                                int n, int K, int M) {
    __shared__ __half As[128][40];   // row stride 80 B (pad 8) -> conflict-free ldmatrix
    __shared__ __half Bs[32][72];    // row stride 144 B (pad 8)
    int t = threadIdx.x;
    int lane = t & 31, wid = t >> 5;
    int warp_m = wid & 3;            // 0..3 -> 32-row slab
    int warp_n = wid >> 2;           // 0..1 -> 32-col slab
    int bm = blockIdx.y * 128;
    int bn = blockIdx.x * 64;

    // global->smem indices
    int ar = t >> 2;                 // 0..63 (A rows; +64 for second half)
    int ac = (t & 3) * 8;            // 0/8/16/24 (halves)
    int brow = t >> 3;               // 0..31
    int bcol = (t & 7) * 8;          // 0..56

    float c[2][4][4];
    #pragma unroll
    for (int mi = 0; mi < 2; mi++)
        #pragma unroll
        for (int ni = 0; ni < 4; ni++)
            #pragma unroll
            for (int q = 0; q < 4; q++) c[mi][ni][q] = 0.f;

    int r0 = bm + ar, r1 = bm + ar + 64;
    const __half* Ap0 = A + (size_t)r0 * K + ac;
    const __half* Ap1 = A + (size_t)r1 * K + ac;
    const __half* Bp  = B + (size_t)brow * M + bn + bcol;
    bool ok0 = r0 < n, ok1 = r1 < n;

    for (int k0 = 0; k0 < K; k0 += 32) {
        uint4 av0 = make_uint4(0u,0u,0u,0u), av1 = make_uint4(0u,0u,0u,0u);
        if (ok0) av0 = *(const uint4*)(Ap0 + k0);
        if (ok1) av1 = *(const uint4*)(Ap1 + k0);
        uint4 bv = *(const uint4*)(Bp + (size_t)k0 * M);
        __syncthreads();
        *(uint4*)&As[ar][ac]      = av0;
        *(uint4*)&As[ar + 64][ac] = av1;
        *(uint4*)&Bs[brow][bcol]  = bv;
        __syncthreads();

        #pragma unroll
        for (int ks = 0; ks < 32; ks += 16) {
            unsigned int afr[2][4], bfr[2][4];
            #pragma unroll
            for (int mi = 0; mi < 2; mi++) {
                unsigned int addr = smem_u32(&As[warp_m * 32 + mi * 16 + (lane & 15)][ks + (lane >> 4) * 8]);
                asm volatile("ldmatrix.sync.aligned.m8n8.x4.shared.b16 {%0,%1,%2,%3}, [%4];"
                    : "=r"(afr[mi][0]), "=r"(afr[mi][1]), "=r"(afr[mi][2]), "=r"(afr[mi][3])
                    : "r"(addr));
            }
            #pragma unroll
            for (int nb = 0; nb < 2; nb++) {
                unsigned int addr = smem_u32(&Bs[ks + (lane & 15)][warp_n * 32 + nb * 16 + (lane >> 4) * 8]);
                asm volatile("ldmatrix.sync.aligned.m8n8.x4.trans.shared.b16 {%0,%1,%2,%3}, [%4];"
                    : "=r"(bfr[nb][0]), "=r"(bfr[nb][1]), "=r"(bfr[nb][2]), "=r"(bfr[nb][3])
                    : "r"(addr));
            }
            #pragma unroll
            for (int mi = 0; mi < 2; mi++)
                #pragma unroll
                for (int ni = 0; ni < 4; ni++) {
                    unsigned int b0 = bfr[ni >> 1][(ni & 1) * 2 + 0];
                    unsigned int b1 = bfr[ni >> 1][(ni & 1) * 2 + 1];
                    asm volatile(
                        "mma.sync.aligned.m16n8k16.row.col.f32.f16.f16.f32 "
                        "{%0,%1,%2,%3}, {%4,%5,%6,%7}, {%8,%9}, {%0,%1,%2,%3};"
                        : "+f"(c[mi][ni][0]), "+f"(c[mi][ni][1]),
                          "+f"(c[mi][ni][2]), "+f"(c[mi][ni][3])
                        : "r"(afr[mi][0]), "r"(afr[mi][1]), "r"(afr[mi][2]), "r"(afr[mi][3]),
                          "r"(b0), "r"(b1));
                }
        }
    }

    // epilogue: fragment layout row = base + lane/4 (+8), col = base + (lane%4)*2
    int rb = bm + warp_m * 32;
    int cbw = bn + warp_n * 32;
    #pragma unroll
    for (int mi = 0; mi < 2; mi++) {
        int rA = rb + mi * 16 + (lane >> 2);
        int rB = rA + 8;
        #pragma unroll
        for (int ni = 0; ni < 4; ni++) {
            int cc = cbw + ni * 8 + (lane & 3) * 2;
            float b0 = 0.f, b1 = 0.f;
            if (BIAS) { b0 = bias[cc]; b1 = bias[cc + 1]; }
            if (HALF_OUT) {
                __half* C = (__half*)Cv;
                if (rA < n) *(__half2*)(C + (size_t)rA * M + cc) =
                    __floats2half2_rn(c[mi][ni][0] + b0, c[mi][ni][1] + b1);
                if (rB < n) *(__half2*)(C + (size_t)rB * M + cc) =
                    __floats2half2_rn(c[mi][ni][2] + b0, c[mi][ni][3] + b1);
            } else {
                float* C = (float*)Cv;
                if (rA < n) *(float2*)(C + (size_t)rA * M + cc) =
                    make_float2(c[mi][ni][0] + b0, c[mi][ni][1] + b1);
                if (rB < n) *(float2*)(C + (size_t)rB * M + cc) =
                    make_float2(c[mi][ni][2] + b0, c[mi][ni][3] + b1);
            }
        }
    }
}

// ---------------- per-node scores layer 1: block per node, warp per head ----------------
__global__ void s1_kernel(const float* __restrict__ a_heads) {
    int node = blockIdx.x;
    int h    = threadIdx.x >> 5;
    int lane = threadIdx.x & 31;
    const __half* base = g_h1 + (size_t)node * F1 + h * 64;
    const float* ah = a_heads + h * 128;
    float v0 = __half2float(base[lane]);
    float v1 = __half2float(base[lane + 32]);
    float ssrc = v0 * ah[lane]      + v1 * ah[lane + 32];
    float sdst = v0 * ah[64 + lane] + v1 * ah[96 + lane];
    #pragma unroll
    for (int off = 16; off; off >>= 1) {
        ssrc += __shfl_xor_sync(0xffffffffu, ssrc, off);
        sdst += __shfl_xor_sync(0xffffffffu, sdst, off);
    }
    if (lane == 0) {
        g_ssrc1[node * NH + h] = ssrc;
        g_sdst1[node * NH + h] = sdst;
    }
}

// ---------------- layer-1 aggregation: warp per node (fp16 gather, fp32 accum) ----------------
__global__ void agg1_kernel() {
    int node = (blockIdx.x * blockDim.x + threadIdx.x) >> 5;
    if (node >= Nn) return;
    int lane = threadIdx.x & 31;
    int hl   = lane & 7;        // head whose weight this lane computes
    int hsel = lane >> 4;       // 0/1: which head within each 128-col chunk

    float ssrc = g_ssrc1[node * NH + hl];
    int beg = g_rowptr[node], end = g_rowptr[node + 1];

    float4 acc[4];
    float  rs[4];
    #pragma unroll
    for (int k = 0; k < 4; k++) { acc[k] = make_float4(0.f,0.f,0.f,0.f); rs[k] = 0.f; }

    for (int j = beg; j < end; j++) {
        int d = g_dst[j];
        float sc = ssrc + g_sdst1[d * NH + hl];
        float lr = sc > 0.f ? sc : ALPHA * sc;
        float w8 = __expf(-lr);
        const __half* hp = g_h1 + (size_t)d * F1;
        #pragma unroll
        for (int k = 0; k < 4; k++) {
            float w = __shfl_sync(0xffffffffu, w8, 2 * k + hsel);
            float4 v = load_half4(hp + k * 128 + lane * 4);
            acc[k].x += w * v.x; acc[k].y += w * v.y;
            acc[k].z += w * v.z; acc[k].w += w * v.w;
            rs[k] += w;
        }
    }

    __half* outp = g_out1 + (size_t)node * F1;
    #pragma unroll
    for (int k = 0; k < 4; k++) {
        float inv = 1.f / (rs[k] + 1e-16f);
        float4 o;
        o.x = acc[k].x * inv; o.y = acc[k].y * inv;
        o.z = acc[k].z * inv; o.w = acc[k].w * inv;
        // ELU
        o.x = o.x > 0.f ? o.x : expm1f(o.x);
        o.y = o.y > 0.f ? o.y : expm1f(o.y);
        o.z = o.z > 0.f ? o.z : expm1f(o.z);
        o.w = o.w > 0.f ? o.w : expm1f(o.w);
        store_half4(outp + k * 128 + lane * 4, o);
    }
}

// ---------------- per-node scores layer 2: warp per node ----------------
__global__ void s2_kernel(const float* __restrict__ a_end) {
    int node = (blockIdx.x * blockDim.x + threadIdx.x) >> 5;
    if (node >= Nn) return;
    int lane = threadIdx.x & 31;
    const float* base = g_h2 + (size_t)node * OUTF;
    float v0 = base[lane], v1 = base[lane + 32];
    float ssrc = v0 * a_end[lane]      + v1 * a_end[lane + 32];
    float sdst = v0 * a_end[64 + lane] + v1 * a_end[96 + lane];
    #pragma unroll
    for (int off = 16; off; off >>= 1) {
        ssrc += __shfl_xor_sync(0xffffffffu, ssrc, off);
        sdst += __shfl_xor_sync(0xffffffffu, sdst, off);
    }
    if (lane == 0) { g_ssrc2[node] = ssrc; g_sdst2[node] = sdst; }
}

// ---------------- layer-2 aggregation + softmax: warp per node ----------------
__global__ void agg2_kernel(float* __restrict__ out) {
    int node = (blockIdx.x * blockDim.x + threadIdx.x) >> 5;
    if (node >= Nn) return;
    int lane = threadIdx.x & 31;

    float ss = g_ssrc2[node];
    int beg = g_rowptr[node], end = g_rowptr[node + 1];
    float a0 = 0.f, a1 = 0.f, rs = 0.f;
    for (int j = beg; j < end; j++) {
        int d = g_dst[j];
        float sc = ss + g_sdst2[d];
        float lr = sc > 0.f ? sc : ALPHA * sc;
        float w = __expf(-lr);
        const float* hp = g_h2 + (size_t)d * OUTF;
        a0 += w * hp[lane];
        a1 += w * hp[lane + 32];
        rs += w;
    }
    float inv = 1.f / (rs + 1e-16f);
    float v0 = a0 * inv, v1 = a1 * inv;

    // softmax over the 64 outputs (2 per lane)
    float m = fmaxf(v0, v1);
    #pragma unroll
    for (int off = 16; off; off >>= 1) m = fmaxf(m, __shfl_xor_sync(0xffffffffu, m, off));
    float e0 = __expf(v0 - m), e1 = __expf(v1 - m);
    float s = e0 + e1;
    #pragma unroll
    for (int off = 16; off; off >>= 1) s += __shfl_xor_sync(0xffffffffu, s, off);
    float invs = 1.f / s;
    out[(size_t)node * OUTF + lane]      = e0 * invs;
    out[(size_t)node * OUTF + lane + 32] = e1 * invs;
}

// ---------------- launch ----------------
extern "C" void kernel_launch(void* const* d_in, const int* in_sizes, int n_in,
                              void* d_out, int out_size) {
    const float* x       = (const float*)d_in[0];
    const int*   edges   = (const int*)  d_in[1];
    const float* W0      = (const float*)d_in[2];
    const float* b0      = (const float*)d_in[3];
    const float* W_heads = (const float*)d_in[4];
    const float* a_heads = (const float*)d_in[5];
    const float* W_end   = (const float*)d_in[6];
    const float* a_end   = (const float*)d_in[7];
    float* out = (float*)d_out;
    const int* src = edges;
    const int* dst = edges + Ee;

    __half *p_xh, *p_xph, *p_h1, *p_out1, *p_W0h, *p_Wcath, *p_Wendh;
    float  *p_h2;
    cudaGetSymbolAddress((void**)&p_xh,    g_x_h);
    cudaGetSymbolAddress((void**)&p_xph,   g_xp_h);
    cudaGetSymbolAddress((void**)&p_h1,    g_h1);
    cudaGetSymbolAddress((void**)&p_out1,  g_out1);
    cudaGetSymbolAddress((void**)&p_h2,    g_h2);
    cudaGetSymbolAddress((void**)&p_W0h,   g_W0h);
    cudaGetSymbolAddress((void**)&p_Wcath, g_Wcat_h);
    cudaGetSymbolAddress((void**)&p_Wendh, g_Wend_h);

    // CSR build
    zero_kernel<<<(Nn + 255) / 256, 256>>>();
    count_kernel<<<(Ee + 255) / 256, 256>>>(src);
    scan_block_kernel<<<NB_SCAN, 1024>>>();
    scan_top_kernel<<<1, 32>>>();
    scan_add_kernel<<<(Nn + 255) / 256, 256>>>();
    scatter_kernel<<<(Ee + 255) / 256, 256>>>(src, dst);

    // fp16 conversions + weight repack
    f2h_kernel<<<(Nn * INF / 4 + 255) / 256, 256>>>(x, p_xh, Nn * INF);
    f2h_kernel<<<(INF * INF / 4 + 255) / 256, 256>>>(W0, p_W0h, INF * INF);
    repack_kernel<<<(INF * F1 + 255) / 256, 256>>>(W_heads);
    f2h_kernel<<<(F1 * OUTF / 4 + 255) / 256, 256>>>(W_end, p_Wendh, F1 * OUTF);

    const int GY = (Nn + 127) / 128;   // 782

    // xp = x @ W0 + b0   (fp16 out)
    mma_gemm_kernel<true, true><<<dim3(INF / 64, GY), 256>>>(p_xh, p_W0h, b0, p_xph, Nn, INF, INF);
    // h1 = xp @ Wcat     (fp16 out, all 8 heads)
    mma_gemm_kernel<true, false><<<dim3(F1 / 64, GY), 256>>>(p_xph, p_Wcath, nullptr, p_h1, Nn, INF, F1);
    // per-node scores, layer 1
    s1_kernel<<<Nn, 256>>>(a_heads);
    // layer-1 aggregation + ELU -> out1 [N,512] (fp16)
    agg1_kernel<<<(Nn + 7) / 8, 256>>>();
    // h2 = out1 @ W_end  (fp32 out)
    mma_gemm_kernel<false, false><<<dim3(OUTF / 64, GY), 256>>>(p_out1, p_Wendh, nullptr, p_h2, Nn, F1, OUTF);
    // per-node scores, layer 2
    s2_kernel<<<(Nn + 7) / 8, 256>>>(a_end);
    // layer-2 aggregation + softmax -> output
    agg2_kernel<<<(Nn + 7) / 8, 256>>>(out);
}

// round 8
// speedup vs baseline: 2.1525x; 1.1217x over previous
#include <cuda_runtime.h>
#include <cuda_fp16.h>
#include <math.h>
#include <stdint.h>

// Problem constants (fixed by the reference)
#define Nn   100000
#define Ee   1600000
#define INF  128
#define HIDF 64
#define NH   8
#define F1   512      // NH*HIDF
#define OUTF 64
#define ALPHA 0.2f
#define NB_SCAN ((Nn + 1023) / 1024)   // 98

// ---------------- device scratch (no allocations allowed) ----------------
__device__ __half g_x_h[(size_t)Nn * INF];        // 25.6 MB
__device__ __half g_xp_h[(size_t)Nn * INF];       // 25.6 MB
__device__ __half g_h1[(size_t)Nn * F1];          // 102.4 MB (~fits L2)
__device__ __half g_out1[(size_t)Nn * F1];        // 102.4 MB
__device__ float  g_h2[Nn * OUTF];                // 25.6 MB
__device__ __half g_W0h[INF * INF];
__device__ __half g_Wcat_h[INF * F1];             // repacked head weights (fp16)
__device__ __half g_Wend_h[F1 * OUTF];
__device__ float  g_ssrc1[Nn * NH];
__device__ float  g_sdst1[Nn * NH];
__device__ float  g_ssrc2[Nn];
__device__ float  g_sdst2[Nn];
__device__ int    g_counts[Nn];
__device__ int    g_fill[Nn];
__device__ int    g_rowptr[Nn + 1];
__device__ int    g_dst[Ee];
__device__ int    g_blksums[128];

// ---------------- fp16 helpers ----------------
__device__ __forceinline__ void store_half4(__half* p, float4 v) {
    __half2 a = __floats2half2_rn(v.x, v.y);
    __half2 b = __floats2half2_rn(v.z, v.w);
    uint2 u;
    u.x = *(unsigned int*)&a;
    u.y = *(unsigned int*)&b;
    *(uint2*)p = u;
}
__device__ __forceinline__ float4 load_half4(const __half* p) {
    uint2 u = *(const uint2*)p;
    __half2 a = *(__half2*)&u.x;
    __half2 b = *(__half2*)&u.y;
    float2 fa = __half22float2(a), fb = __half22float2(b);
    return make_float4(fa.x, fa.y, fb.x, fb.y);
}
__device__ __forceinline__ unsigned int smem_u32(const void* p) {
    return (unsigned int)__cvta_generic_to_shared(p);
}

// ---------------- CSR construction ----------------
// Also zeroes the layer-1 score accumulators (needed by the fused GEMM2 epilogue).
__global__ void zero_kernel() {
    int i = blockIdx.x * blockDim.x + threadIdx.x;
    if (i < Nn) { g_counts[i] = 0; g_fill[i] = 0; }
    if (i < Nn * NH) { g_ssrc1[i] = 0.f; g_sdst1[i] = 0.f; }
}

__global__ void count_kernel(const int* __restrict__ src) {
    int e = blockIdx.x * blockDim.x + threadIdx.x;
    if (e < Ee) atomicAdd(&g_counts[src[e]], 1);
}

__global__ void scan_block_kernel() {
    __shared__ int sh[1024];
    int i = blockIdx.x * 1024 + threadIdx.x;
    int v = (i < Nn) ? g_counts[i] : 0;
    sh[threadIdx.x] = v;
    __syncthreads();
    #pragma unroll
    for (int off = 1; off < 1024; off <<= 1) {
        int t = (threadIdx.x >= off) ? sh[threadIdx.x - off] : 0;
        __syncthreads();
        sh[threadIdx.x] += t;
        __syncthreads();
    }
    if (i < Nn) g_rowptr[i] = sh[threadIdx.x] - v;   // exclusive within block
    if (threadIdx.x == 1023) g_blksums[blockIdx.x] = sh[1023];
}

__global__ void scan_top_kernel() {
    __shared__ int sh[128];
    int i = threadIdx.x;
    int v = (i < NB_SCAN) ? g_blksums[i] : 0;
    sh[i] = v;
    __syncthreads();
    #pragma unroll
    for (int off = 1; off < 128; off <<= 1) {
        int t = (i >= off) ? sh[i - off] : 0;
        __syncthreads();
        sh[i] += t;
        __syncthreads();
    }
    if (i < NB_SCAN) g_blksums[i] = sh[i] - v;   // exclusive
}

__global__ void scan_add_kernel() {
    int i = blockIdx.x * blockDim.x + threadIdx.x;
    if (i < Nn) g_rowptr[i] += g_blksums[i >> 10];
    if (i == 0) g_rowptr[Nn] = Ee;
}

__global__ void scatter_kernel(const int* __restrict__ src, const int* __restrict__ dst) {
    int e = blockIdx.x * blockDim.x + threadIdx.x;
    if (e < Ee) {
        int s = src[e];
        int pos = g_rowptr[s] + atomicAdd(&g_fill[s], 1);
        g_dst[pos] = dst[e];
    }
}

// ---------------- conversions ----------------
__global__ void f2h_kernel(const float* __restrict__ in, __half* __restrict__ out, int nElem) {
    int i = (blockIdx.x * blockDim.x + threadIdx.x) * 4;
    if (i < nElem) {
        float4 v = *(const float4*)(in + i);
        store_half4(out + i, v);
    }
}

// Wcat_h[i][h*64+j] = W_heads[h][i][j]   (fp16)
__global__ void repack_kernel(const float* __restrict__ W_heads) {
    int t = blockIdx.x * blockDim.x + threadIdx.x;
    if (t >= INF * F1) return;
    int i = t / F1;
    int c = t - i * F1;
    int h = c >> 6;
    int j = c & 63;
    g_Wcat_h[t] = __float2half(W_heads[(h * INF + i) * HIDF + j]);
}

// ---------------- tensor-core GEMM: C[n,M] = A[n,K] @ B[K,M] ----------------
// fp16 A/B, fp32 accumulate. BM=128, BN=64, BK=32, 256 threads (8 warps, 4x2).
// K % 32 == 0, M % 64 == 0 (true for all call sites).
// SCORES (GEMM2 only): BN==64 tile == one head; fused s_src/s_dst epilogue via
// shfl-reduce + atomicAdd into pre-zeroed g_ssrc1/g_sdst1.
// STREAM_A: evict-first A loads (A is read exactly once; don't pollute L2).
template<bool HALF_OUT, bool BIAS, bool SCORES, bool STREAM_A>
__global__ void mma_gemm_kernel(const __half* __restrict__ A, const __half* __restrict__ B,
                                const float* __restrict__ bias, void* __restrict__ Cv,
                                const float* __restrict__ a_heads,
                                int n, int K, int M) {
    __shared__ __half As[128][40];   // row stride 80 B (pad 8) -> conflict-free ldmatrix
    __shared__ __half Bs[32][72];    // row stride 144 B (pad 8)
    int t = threadIdx.x;
    int lane = t & 31, wid = t >> 5;
    int warp_m = wid & 3;            // 0..3 -> 32-row slab
    int warp_n = wid >> 2;           // 0..1 -> 32-col slab
    int bm = blockIdx.y * 128;
    int bn = blockIdx.x * 64;

    // global->smem indices
    int ar = t >> 2;                 // 0..63 (A rows; +64 for second half)
    int ac = (t & 3) * 8;            // 0/8/16/24 (halves)
    int brow = t >> 3;               // 0..31
    int bcol = (t & 7) * 8;          // 0..56

    float c[2][4][4];
    #pragma unroll
    for (int mi = 0; mi < 2; mi++)
        #pragma unroll
        for (int ni = 0; ni < 4; ni++)
            #pragma unroll
            for (int q = 0; q < 4; q++) c[mi][ni][q] = 0.f;

    int r0 = bm + ar, r1 = bm + ar + 64;
    const __half* Ap0 = A + (size_t)r0 * K + ac;
    const __half* Ap1 = A + (size_t)r1 * K + ac;
    const __half* Bp  = B + (size_t)brow * M + bn + bcol;
    bool ok0 = r0 < n, ok1 = r1 < n;

    // prefetch iteration 0
    uint4 av0 = make_uint4(0u,0u,0u,0u), av1 = make_uint4(0u,0u,0u,0u);
    if (ok0) av0 = STREAM_A ? __ldcs((const uint4*)Ap0) : *(const uint4*)Ap0;
    if (ok1) av1 = STREAM_A ? __ldcs((const uint4*)Ap1) : *(const uint4*)Ap1;
    uint4 bv = *(const uint4*)Bp;

    for (int k0 = 0; k0 < K; k0 += 32) {
        __syncthreads();
        *(uint4*)&As[ar][ac]      = av0;
        *(uint4*)&As[ar + 64][ac] = av1;
        *(uint4*)&Bs[brow][bcol]  = bv;
        __syncthreads();

        // prefetch next iteration's global data before compute (hide latency)
        int kn = k0 + 32;
        if (kn < K) {
            av0 = make_uint4(0u,0u,0u,0u); av1 = make_uint4(0u,0u,0u,0u);
            if (ok0) av0 = STREAM_A ? __ldcs((const uint4*)(Ap0 + kn)) : *(const uint4*)(Ap0 + kn);
            if (ok1) av1 = STREAM_A ? __ldcs((const uint4*)(Ap1 + kn)) : *(const uint4*)(Ap1 + kn);
            bv = *(const uint4*)(Bp + (size_t)kn * M);
        }

        #pragma unroll
        for (int ks = 0; ks < 32; ks += 16) {
            unsigned int afr[2][4], bfr[2][4];
            #pragma unroll
            for (int mi = 0; mi < 2; mi++) {
                unsigned int addr = smem_u32(&As[warp_m * 32 + mi * 16 + (lane & 15)][ks + (lane >> 4) * 8]);
                asm volatile("ldmatrix.sync.aligned.m8n8.x4.shared.b16 {%0,%1,%2,%3}, [%4];"
                    : "=r"(afr[mi][0]), "=r"(afr[mi][1]), "=r"(afr[mi][2]), "=r"(afr[mi][3])
                    : "r"(addr));
            }
            #pragma unroll
            for (int nb = 0; nb < 2; nb++) {
                unsigned int addr = smem_u32(&Bs[ks + (lane & 15)][warp_n * 32 + nb * 16 + (lane >> 4) * 8]);
                asm volatile("ldmatrix.sync.aligned.m8n8.x4.trans.shared.b16 {%0,%1,%2,%3}, [%4];"
                    : "=r"(bfr[nb][0]), "=r"(bfr[nb][1]), "=r"(bfr[nb][2]), "=r"(bfr[nb][3])
                    : "r"(addr));
            }
            #pragma unroll
            for (int mi = 0; mi < 2; mi++)
                #pragma unroll
                for (int ni = 0; ni < 4; ni++) {
                    unsigned int b0 = bfr[ni >> 1][(ni & 1) * 2 + 0];
                    unsigned int b1 = bfr[ni >> 1][(ni & 1) * 2 + 1];
                    asm volatile(
                        "mma.sync.aligned.m16n8k16.row.col.f32.f16.f16.f32 "
                        "{%0,%1,%2,%3}, {%4,%5,%6,%7}, {%8,%9}, {%0,%1,%2,%3};"
                        : "+f"(c[mi][ni][0]), "+f"(c[mi][ni][1]),
                          "+f"(c[mi][ni][2]), "+f"(c[mi][ni][3])
                        : "r"(afr[mi][0]), "r"(afr[mi][1]), "r"(afr[mi][2]), "r"(afr[mi][3]),
                          "r"(b0), "r"(b1));
                }
        }
    }

    // epilogue: fragment layout row = base + lane/4 (+8), col = base + (lane%4)*2
    int rb = bm + warp_m * 32;
    int cbw = bn + warp_n * 32;

    // attention-vector slices for SCORES (head h = blockIdx.x; col-in-head = cc - bn)
    float a_s[4][2], a_d[4][2];
    if (SCORES) {
        int h = blockIdx.x;
        #pragma unroll
        for (int ni = 0; ni < 4; ni++) {
            int colh = warp_n * 32 + ni * 8 + (lane & 3) * 2;
            float2 vs = *(const float2*)(a_heads + h * 128 + colh);
            float2 vd = *(const float2*)(a_heads + h * 128 + 64 + colh);
            a_s[ni][0] = vs.x; a_s[ni][1] = vs.y;
            a_d[ni][0] = vd.x; a_d[ni][1] = vd.y;
        }
    }

    #pragma unroll
    for (int mi = 0; mi < 2; mi++) {
        int rA = rb + mi * 16 + (lane >> 2);
        int rB = rA + 8;
        float psA = 0.f, pdA = 0.f, psB = 0.f, pdB = 0.f;
        #pragma unroll
        for (int ni = 0; ni < 4; ni++) {
            int cc = cbw + ni * 8 + (lane & 3) * 2;
            float b0 = 0.f, b1 = 0.f;
            if (BIAS) { b0 = bias[cc]; b1 = bias[cc + 1]; }
            if (HALF_OUT) {
                __half* C = (__half*)Cv;
                if (rA < n) *(__half2*)(C + (size_t)rA * M + cc) =
                    __floats2half2_rn(c[mi][ni][0] + b0, c[mi][ni][1] + b1);
                if (rB < n) *(__half2*)(C + (size_t)rB * M + cc) =
                    __floats2half2_rn(c[mi][ni][2] + b0, c[mi][ni][3] + b1);
            } else {
                float* C = (float*)Cv;
                if (rA < n) *(float2*)(C + (size_t)rA * M + cc) =
                    make_float2(c[mi][ni][0] + b0, c[mi][ni][1] + b1);
                if (rB < n) *(float2*)(C + (size_t)rB * M + cc) =
                    make_float2(c[mi][ni][2] + b0, c[mi][ni][3] + b1);
            }
            if (SCORES) {
                psA += c[mi][ni][0] * a_s[ni][0] + c[mi][ni][1] * a_s[ni][1];
                pdA += c[mi][ni][0] * a_d[ni][0] + c[mi][ni][1] * a_d[ni][1];
                psB += c[mi][ni][2] * a_s[ni][0] + c[mi][ni][3] * a_s[ni][1];
                pdB += c[mi][ni][2] * a_d[ni][0] + c[mi][ni][3] * a_d[ni][1];
            }
        }
        if (SCORES) {
            // reduce over the 4 lanes sharing each row (lane&3 varies)
            #pragma unroll
            for (int off = 1; off <= 2; off <<= 1) {
                psA += __shfl_xor_sync(0xffffffffu, psA, off);
                pdA += __shfl_xor_sync(0xffffffffu, pdA, off);
                psB += __shfl_xor_sync(0xffffffffu, psB, off);
                pdB += __shfl_xor_sync(0xffffffffu, pdB, off);
            }
            if ((lane & 3) == 0) {
                int h = blockIdx.x;
                if (rA < n) {
                    atomicAdd(&g_ssrc1[rA * NH + h], psA);
                    atomicAdd(&g_sdst1[rA * NH + h], pdA);
                }
                if (rB < n) {
                    atomicAdd(&g_ssrc1[rB * NH + h], psB);
                    atomicAdd(&g_sdst1[rB * NH + h], pdB);
                }
            }
        }
    }
}

// ---------------- layer-1 aggregation: warp per node (fp16 gather, fp32 accum) ----------------
__global__ void agg1_kernel() {
    int node = (blockIdx.x * blockDim.x + threadIdx.x) >> 5;
    if (node >= Nn) return;
    int lane = threadIdx.x & 31;
    int hl   = lane & 7;        // head whose weight this lane computes
    int hsel = lane >> 4;       // 0/1: which head within each 128-col chunk

    float ssrc = g_ssrc1[node * NH + hl];
    int beg = g_rowptr[node], end = g_rowptr[node + 1];

    float4 acc[4];
    float  rs[4];
    #pragma unroll
    for (int k = 0; k < 4; k++) { acc[k] = make_float4(0.f,0.f,0.f,0.f); rs[k] = 0.f; }

    for (int j = beg; j < end; j++) {
        int d = g_dst[j];
        float sc = ssrc + g_sdst1[d * NH + hl];
        float lr = sc > 0.f ? sc : ALPHA * sc;
        float w8 = __expf(-lr);
        const __half* hp = g_h1 + (size_t)d * F1;
        #pragma unroll
        for (int k = 0; k < 4; k++) {
            float w = __shfl_sync(0xffffffffu, w8, 2 * k + hsel);
            float4 v = load_half4(hp + k * 128 + lane * 4);
            acc[k].x += w * v.x; acc[k].y += w * v.y;
            acc[k].z += w * v.z; acc[k].w += w * v.w;
            rs[k] += w;
        }
    }

    __half* outp = g_out1 + (size_t)node * F1;
    #pragma unroll
    for (int k = 0; k < 4; k++) {
        float inv = 1.f / (rs[k] + 1e-16f);
        float4 o;
        o.x = acc[k].x * inv; o.y = acc[k].y * inv;
        o.z = acc[k].z * inv; o.w = acc[k].w * inv;
        // ELU
        o.x = o.x > 0.f ? o.x : expm1f(o.x);
        o.y = o.y > 0.f ? o.y : expm1f(o.y);
        o.z = o.z > 0.f ? o.z : expm1f(o.z);
        o.w = o.w > 0.f ? o.w : expm1f(o.w);
        // evict-first store: out1 is write-once here, read-once by GEMM3;
        // keep the h1 gather working set in L2 instead.
        __half2 ha = __floats2half2_rn(o.x, o.y);
        __half2 hb = __floats2half2_rn(o.z, o.w);
        uint2 u;
        u.x = *(unsigned int*)&ha;
        u.y = *(unsigned int*)&hb;
        __stcs((uint2*)(outp + k * 128 + lane * 4), u);
    }
}

// ---------------- per-node scores layer 2: warp per node ----------------
__global__ void s2_kernel(const float* __restrict__ a_end) {
    int node = (blockIdx.x * blockDim.x + threadIdx.x) >> 5;
    if (node >= Nn) return;
    int lane = threadIdx.x & 31;
    const float* base = g_h2 + (size_t)node * OUTF;
    float v0 = base[lane], v1 = base[lane + 32];
    float ssrc = v0 * a_end[lane]      + v1 * a_end[lane + 32];
    float sdst = v0 * a_end[64 + lane] + v1 * a_end[96 + lane];
    #pragma unroll
    for (int off = 16; off; off >>= 1) {
        ssrc += __shfl_xor_sync(0xffffffffu, ssrc, off);
        sdst += __shfl_xor_sync(0xffffffffu, sdst, off);
    }
    if (lane == 0) { g_ssrc2[node] = ssrc; g_sdst2[node] = sdst; }
}

// ---------------- layer-2 aggregation + softmax: warp per node ----------------
__global__ void agg2_kernel(float* __restrict__ out) {
    int node = (blockIdx.x * blockDim.x + threadIdx.x) >> 5;
    if (node >= Nn) return;
    int lane = threadIdx.x & 31;

    float ss = g_ssrc2[node];
    int beg = g_rowptr[node], end = g_rowptr[node + 1];
    float a0 = 0.f, a1 = 0.f, rs = 0.f;
    for (int j = beg; j < end; j++) {
        int d = g_dst[j];
        float sc = ss + g_sdst2[d];
        float lr = sc > 0.f ? sc : ALPHA * sc;
        float w = __expf(-lr);
        const float* hp = g_h2 + (size_t)d * OUTF;
        a0 += w * hp[lane];
        a1 += w * hp[lane + 32];
        rs += w;
    }
    float inv = 1.f / (rs + 1e-16f);
    float v0 = a0 * inv, v1 = a1 * inv;

    // softmax over the 64 outputs (2 per lane)
    float m = fmaxf(v0, v1);
    #pragma unroll
    for (int off = 16; off; off >>= 1) m = fmaxf(m, __shfl_xor_sync(0xffffffffu, m, off));
    float e0 = __expf(v0 - m), e1 = __expf(v1 - m);
    float s = e0 + e1;
    #pragma unroll
    for (int off = 16; off; off >>= 1) s += __shfl_xor_sync(0xffffffffu, s, off);
    float invs = 1.f / s;
    out[(size_t)node * OUTF + lane]      = e0 * invs;
    out[(size_t)node * OUTF + lane + 32] = e1 * invs;
}

// ---------------- launch ----------------
extern "C" void kernel_launch(void* const* d_in, const int* in_sizes, int n_in,
                              void* d_out, int out_size) {
    const float* x       = (const float*)d_in[0];
    const int*   edges   = (const int*)  d_in[1];
    const float* W0      = (const float*)d_in[2];
    const float* b0      = (const float*)d_in[3];
    const float* W_heads = (const float*)d_in[4];
    const float* a_heads = (const float*)d_in[5];
    const float* W_end   = (const float*)d_in[6];
    const float* a_end   = (const float*)d_in[7];
    float* out = (float*)d_out;
    const int* src = edges;
    const int* dst = edges + Ee;

    __half *p_xh, *p_xph, *p_h1, *p_out1, *p_W0h, *p_Wcath, *p_Wendh;
    float  *p_h2;
    cudaGetSymbolAddress((void**)&p_xh,    g_x_h);
    cudaGetSymbolAddress((void**)&p_xph,   g_xp_h);
    cudaGetSymbolAddress((void**)&p_h1,    g_h1);
    cudaGetSymbolAddress((void**)&p_out1,  g_out1);
    cudaGetSymbolAddress((void**)&p_h2,    g_h2);
    cudaGetSymbolAddress((void**)&p_W0h,   g_W0h);
    cudaGetSymbolAddress((void**)&p_Wcath, g_Wcat_h);
    cudaGetSymbolAddress((void**)&p_Wendh, g_Wend_h);

    // CSR build + zero score accumulators
    zero_kernel<<<(Nn * NH + 255) / 256, 256>>>();
    count_kernel<<<(Ee + 255) / 256, 256>>>(src);
    scan_block_kernel<<<NB_SCAN, 1024>>>();
    scan_top_kernel<<<1, 128>>>();
    scan_add_kernel<<<(Nn + 255) / 256, 256>>>();
    scatter_kernel<<<(Ee + 255) / 256, 256>>>(src, dst);

    // fp16 conversions + weight repack
    f2h_kernel<<<(Nn * INF / 4 + 255) / 256, 256>>>(x, p_xh, Nn * INF);
    f2h_kernel<<<(INF * INF / 4 + 255) / 256, 256>>>(W0, p_W0h, INF * INF);
    repack_kernel<<<(INF * F1 + 255) / 256, 256>>>(W_heads);
    f2h_kernel<<<(F1 * OUTF / 4 + 255) / 256, 256>>>(W_end, p_Wendh, F1 * OUTF);

    const int GY = (Nn + 127) / 128;   // 782

    // xp = x @ W0 + b0   (fp16 out)
    mma_gemm_kernel<true, true, false, false><<<dim3(INF / 64, GY), 256>>>(
        p_xh, p_W0h, b0, p_xph, nullptr, Nn, INF, INF);
    // h1 = xp @ Wcat     (fp16 out, all 8 heads) + fused s1 scores
    mma_gemm_kernel<true, false, true, false><<<dim3(F1 / 64, GY), 256>>>(
        p_xph, p_Wcath, nullptr, p_h1, a_heads, Nn, INF, F1);
    // layer-1 aggregation + ELU -> out1 [N,512] (fp16)
    agg1_kernel<<<(Nn + 7) / 8, 256>>>();
    // h2 = out1 @ W_end  (fp32 out; A is read-once -> streaming loads)
    mma_gemm_kernel<false, false, false, true><<<dim3(OUTF / 64, GY), 256>>>(
        p_out1, p_Wendh, nullptr, p_h2, nullptr, Nn, F1, OUTF);
    // per-node scores, layer 2
    s2_kernel<<<(Nn + 7) / 8, 256>>>(a_end);
    // layer-2 aggregation + softmax -> output
    agg2_kernel<<<(Nn + 7) / 8, 256>>>(out);
}